// round 1
// baseline (speedup 1.0000x reference)
#include <cuda_runtime.h>
#include <math.h>

// Problem constants
#define B_  2
#define T_  2048
#define C_  768
#define H_  12
#define D_  64
#define BH_ (B_*H_)          // 24
#define ROWS_ (B_*T_)        // 4096
#define QKV_ELEMS (BH_*T_*D_)  // 3,145,728
#define Y_ELEMS   (B_*T_*C_)   // 3,145,728
#define ATT_ELEMS ((size_t)BH_*T_*T_)  // 100,663,296
#define SCALE_ 0.125f        // 1/sqrt(64)

// Scratch (device globals: no allocation allowed)
__device__ float g_q[QKV_ELEMS];
__device__ float g_k[QKV_ELEMS];
__device__ float g_v[QKV_ELEMS];
__device__ float g_y[QKV_ELEMS];

// ---------------------------------------------------------------------------
// K1: QKV projection.  out[row, col] = sum_c x[row,c] * W[col,c]
// A (4096x768) row-major k-contiguous, B = W (768x768) row-major k-contiguous.
// 128x128 tile, BK=8, 256 threads, 8x8 per thread.
// Epilogue scatters into (b,h,t,d) layout. blockIdx.z selects Wq/Wk/Wv.
// ---------------------------------------------------------------------------
__global__ __launch_bounds__(256) void qkv_gemm_kernel(
    const float* __restrict__ x,
    const float* __restrict__ Wq,
    const float* __restrict__ Wk,
    const float* __restrict__ Wv)
{
    const float* W = (blockIdx.z == 0) ? Wq : (blockIdx.z == 1 ? Wk : Wv);
    float* dst = (blockIdx.z == 0) ? g_q : (blockIdx.z == 1 ? g_k : g_v);

    __shared__ float As[8][128];
    __shared__ float Bs[8][128];

    const int row0 = blockIdx.y * 128;
    const int col0 = blockIdx.x * 128;
    const int tid = threadIdx.x;
    const int ar = tid >> 1;
    const int ac = (tid & 1) * 4;
    const int rb = (tid >> 4) << 3;
    const int cb = (tid & 15) << 3;

    float acc[8][8];
    #pragma unroll
    for (int i = 0; i < 8; i++)
        #pragma unroll
        for (int j = 0; j < 8; j++) acc[i][j] = 0.0f;

    for (int k0 = 0; k0 < C_; k0 += 8) {
        float4 a4 = *(const float4*)(x + (size_t)(row0 + ar) * C_ + k0 + ac);
        float4 b4 = *(const float4*)(W + (size_t)(col0 + ar) * C_ + k0 + ac);
        As[ac + 0][ar] = a4.x; As[ac + 1][ar] = a4.y;
        As[ac + 2][ar] = a4.z; As[ac + 3][ar] = a4.w;
        Bs[ac + 0][ar] = b4.x; Bs[ac + 1][ar] = b4.y;
        Bs[ac + 2][ar] = b4.z; Bs[ac + 3][ar] = b4.w;
        __syncthreads();

        #pragma unroll
        for (int kk = 0; kk < 8; kk++) {
            float a[8], b[8];
            #pragma unroll
            for (int i = 0; i < 8; i++) a[i] = As[kk][rb + i];
            #pragma unroll
            for (int j = 0; j < 8; j++) b[j] = Bs[kk][cb + j];
            #pragma unroll
            for (int i = 0; i < 8; i++)
                #pragma unroll
                for (int j = 0; j < 8; j++)
                    acc[i][j] = fmaf(a[i], b[j], acc[i][j]);
        }
        __syncthreads();
    }

    #pragma unroll
    for (int i = 0; i < 8; i++) {
        const int row = row0 + rb + i;
        const int b = row >> 11;
        const int t = row & (T_ - 1);
        #pragma unroll
        for (int j = 0; j < 8; j++) {
            const int col = col0 + cb + j;
            const int h = col >> 6;
            const int d = col & 63;
            dst[(((size_t)(b * H_ + h)) * T_ + t) * D_ + d] = acc[i][j];
        }
    }
}

// ---------------------------------------------------------------------------
// K2: RoPE on g_q / g_k, in place. One warp per (b,h,t) row, lanes 0..31 = d.
//   rot[d] = (d<16 ? -u[d+16] : u[d-16]) == sign * shfl_xor(u, 16)
// ---------------------------------------------------------------------------
__global__ __launch_bounds__(256) void rope_kernel()
{
    const int lane = threadIdx.x & 31;
    const int wid = threadIdx.x >> 5;
    const int row = blockIdx.x * 8 + wid;      // 0 .. BH_*T_-1
    float* base = ((blockIdx.y == 0) ? g_q : g_k) + (size_t)row * D_;
    const int t = row & (T_ - 1);

    const double dinv = pow(10000.0, -(double)lane / 32.0);
    const float inv = (float)dinv;
    const float ang = (float)t * inv;
    const float c = cosf(ang);
    const float s = sinf(ang);

    const float u = base[lane];
    const float part = __shfl_xor_sync(0xffffffffu, u, 16);
    const float rot = (lane < 16) ? -part : part;
    base[lane] = fmaf(u, c, rot * s);
}

// ---------------------------------------------------------------------------
// K3: raw scores (scaled qk^T + rel_bias), lower-triangle tiles only.
// Block = (qtile, bh). 64x64 tile, 256 threads, 4x4 microtile.
// Q/K stored d-major in smem for conflict-free inner product.
// ---------------------------------------------------------------------------
__global__ __launch_bounds__(256) void scores_kernel(
    const float* __restrict__ rel_bias, float* __restrict__ att)
{
    const int qt = blockIdx.x;     // 0..31
    const int bh = blockIdx.y;     // 0..23
    const int h = bh % H_;
    const float* qbase = g_q + (size_t)bh * T_ * D_;
    const float* kbase = g_k + (size_t)bh * T_ * D_;

    __shared__ float Qs[64][65];   // [d][t]
    __shared__ float Ks[64][65];   // [d][t]

    const int tid = threadIdx.x;
    const int ty = tid >> 4;
    const int tx = tid & 15;
    const int q0 = qt * 64;

    for (int i = tid; i < 4096; i += 256) {
        const int t = i >> 6, d = i & 63;
        Qs[d][t] = qbase[(size_t)(q0 + t) * D_ + d];
    }

    for (int kt = 0; kt <= qt; kt++) {
        __syncthreads();
        const int k0 = kt * 64;
        for (int i = tid; i < 4096; i += 256) {
            const int t = i >> 6, d = i & 63;
            Ks[d][t] = kbase[(size_t)(k0 + t) * D_ + d];
        }
        __syncthreads();

        float acc[4][4];
        #pragma unroll
        for (int i = 0; i < 4; i++)
            #pragma unroll
            for (int j = 0; j < 4; j++) acc[i][j] = 0.0f;

        #pragma unroll 8
        for (int c = 0; c < 64; c++) {
            float qa[4], kb[4];
            #pragma unroll
            for (int i = 0; i < 4; i++) qa[i] = Qs[c][ty * 4 + i];
            #pragma unroll
            for (int j = 0; j < 4; j++) kb[j] = Ks[c][tx * 4 + j];
            #pragma unroll
            for (int i = 0; i < 4; i++)
                #pragma unroll
                for (int j = 0; j < 4; j++)
                    acc[i][j] = fmaf(qa[i], kb[j], acc[i][j]);
        }

        #pragma unroll
        for (int i = 0; i < 4; i++) {
            const int qi = q0 + ty * 4 + i;
            float4 sv;
            float* svp = &sv.x;
            #pragma unroll
            for (int j = 0; j < 4; j++) {
                const int ki = k0 + tx * 4 + j;
                float sval;
                if (ki <= qi) {
                    sval = fmaf(acc[i][j], SCALE_,
                                __ldg(&rel_bias[(size_t)(qi - ki + T_ - 1) * H_ + h]));
                } else {
                    sval = -1e30f;   // inside diagonal tile; never read by softmax
                }
                svp[j] = sval;
            }
            *(float4*)(att + ((size_t)bh * T_ + qi) * T_ + k0 + tx * 4) = sv;
        }
    }
}

// ---------------------------------------------------------------------------
// K4: row softmax over the causal prefix; zeros above the diagonal.
// One block per (b,h,q) row; row fits in smem (2048 fp32 = 8 KB).
// ---------------------------------------------------------------------------
__global__ __launch_bounds__(256) void softmax_kernel(float* __restrict__ att)
{
    const int row = blockIdx.x;           // 0 .. BH_*T_-1
    const int q = row & (T_ - 1);
    const int len = q + 1;
    float* p = att + (size_t)row * T_;

    __shared__ float buf[T_];
    __shared__ float red[256];
    const int tid = threadIdx.x;

    float m = -1e30f;
    for (int i = tid; i < len; i += 256) {
        const float v = p[i];
        buf[i] = v;
        m = fmaxf(m, v);
    }
    red[tid] = m;
    __syncthreads();
    #pragma unroll
    for (int s = 128; s > 0; s >>= 1) {
        if (tid < s) red[tid] = fmaxf(red[tid], red[tid + s]);
        __syncthreads();
    }
    m = red[0];
    __syncthreads();

    float sum = 0.0f;
    for (int i = tid; i < len; i += 256) {
        const float e = expf(buf[i] - m);
        buf[i] = e;
        sum += e;
    }
    red[tid] = sum;
    __syncthreads();
    #pragma unroll
    for (int s = 128; s > 0; s >>= 1) {
        if (tid < s) red[tid] += red[tid + s];
        __syncthreads();
    }
    const float inv = 1.0f / red[0];
    __syncthreads();

    for (int i = tid; i < T_; i += 256) {
        p[i] = (i < len) ? buf[i] * inv : 0.0f;
    }
}

// ---------------------------------------------------------------------------
// K5: y = att @ v  per (b,h).  Block = (qtile, bh), 64x64 output (64 q x 64 d),
// BK=16, 4x4 microtile.  k-loop truncated to causal range.
// ---------------------------------------------------------------------------
__global__ __launch_bounds__(256) void av_kernel(const float* __restrict__ att)
{
    const int qt = blockIdx.x;
    const int bh = blockIdx.y;
    const float* vbase = g_v + (size_t)bh * T_ * D_;
    float* ybase = g_y + (size_t)bh * T_ * D_;

    __shared__ float As[64][17];
    __shared__ float Bs[16][64];

    const int tid = threadIdx.x;
    const int ty = tid >> 4;
    const int tx = tid & 15;
    const int q0 = qt * 64;
    const float* attb = att + ((size_t)bh * T_ + q0) * T_;

    float acc[4][4];
    #pragma unroll
    for (int i = 0; i < 4; i++)
        #pragma unroll
        for (int j = 0; j < 4; j++) acc[i][j] = 0.0f;

    const int kend = (qt + 1) * 64;
    for (int k0 = 0; k0 < kend; k0 += 16) {
        {
            const int r = tid >> 2;
            const int c4 = (tid & 3) * 4;
            float4 v4 = *(const float4*)(attb + (size_t)r * T_ + k0 + c4);
            As[r][c4 + 0] = v4.x; As[r][c4 + 1] = v4.y;
            As[r][c4 + 2] = v4.z; As[r][c4 + 3] = v4.w;
        }
        {
            const int r = tid >> 4;
            const int c4 = (tid & 15) * 4;
            float4 v4 = *(const float4*)(vbase + (size_t)(k0 + r) * D_ + c4);
            Bs[r][c4 + 0] = v4.x; Bs[r][c4 + 1] = v4.y;
            Bs[r][c4 + 2] = v4.z; Bs[r][c4 + 3] = v4.w;
        }
        __syncthreads();

        #pragma unroll
        for (int kk = 0; kk < 16; kk++) {
            float a[4], b[4];
            #pragma unroll
            for (int i = 0; i < 4; i++) a[i] = As[ty * 4 + i][kk];
            #pragma unroll
            for (int j = 0; j < 4; j++) b[j] = Bs[kk][tx * 4 + j];
            #pragma unroll
            for (int i = 0; i < 4; i++)
                #pragma unroll
                for (int j = 0; j < 4; j++)
                    acc[i][j] = fmaf(a[i], b[j], acc[i][j]);
        }
        __syncthreads();
    }

    #pragma unroll
    for (int i = 0; i < 4; i++)
        #pragma unroll
        for (int j = 0; j < 4; j++)
            ybase[(size_t)(q0 + ty * 4 + i) * D_ + tx * 4 + j] = acc[i][j];
}

// ---------------------------------------------------------------------------
// K6: output projection.  out[row,col] = sum_c ybht[row,c] * Wp[col,c] + bp[col]
// ybht gathered from (b,h,t,d) layout; 8-wide k-tiles never cross a head.
// ---------------------------------------------------------------------------
__global__ __launch_bounds__(256) void proj_kernel(
    const float* __restrict__ Wp, const float* __restrict__ bp,
    float* __restrict__ out)
{
    __shared__ float As[8][128];
    __shared__ float Bs[8][128];

    const int row0 = blockIdx.y * 128;
    const int col0 = blockIdx.x * 128;
    const int tid = threadIdx.x;
    const int ar = tid >> 1;
    const int ac = (tid & 1) * 4;
    const int rb = (tid >> 4) << 3;
    const int cb = (tid & 15) << 3;

    float acc[8][8];
    #pragma unroll
    for (int i = 0; i < 8; i++)
        #pragma unroll
        for (int j = 0; j < 8; j++) acc[i][j] = 0.0f;

    const int arow = row0 + ar;
    const int b = arow >> 11;
    const int t = arow & (T_ - 1);

    for (int k0 = 0; k0 < C_; k0 += 8) {
        const int c = k0 + ac;
        const int h = c >> 6;
        const int d = c & 63;
        float4 a4 = *(const float4*)(g_y + (((size_t)(b * H_ + h)) * T_ + t) * D_ + d);
        float4 b4 = *(const float4*)(Wp + (size_t)(col0 + ar) * C_ + k0 + ac);
        As[ac + 0][ar] = a4.x; As[ac + 1][ar] = a4.y;
        As[ac + 2][ar] = a4.z; As[ac + 3][ar] = a4.w;
        Bs[ac + 0][ar] = b4.x; Bs[ac + 1][ar] = b4.y;
        Bs[ac + 2][ar] = b4.z; Bs[ac + 3][ar] = b4.w;
        __syncthreads();

        #pragma unroll
        for (int kk = 0; kk < 8; kk++) {
            float a[8], bb[8];
            #pragma unroll
            for (int i = 0; i < 8; i++) a[i] = As[kk][rb + i];
            #pragma unroll
            for (int j = 0; j < 8; j++) bb[j] = Bs[kk][cb + j];
            #pragma unroll
            for (int i = 0; i < 8; i++)
                #pragma unroll
                for (int j = 0; j < 8; j++)
                    acc[i][j] = fmaf(a[i], bb[j], acc[i][j]);
        }
        __syncthreads();
    }

    #pragma unroll
    for (int i = 0; i < 8; i++) {
        const int row = row0 + rb + i;
        #pragma unroll
        for (int j = 0; j < 8; j++) {
            const int col = col0 + cb + j;
            out[(size_t)row * C_ + col] = acc[i][j] + __ldg(&bp[col]);
        }
    }
}

// ---------------------------------------------------------------------------
// Launch
// ---------------------------------------------------------------------------
extern "C" void kernel_launch(void* const* d_in, const int* in_sizes, int n_in,
                              void* d_out, int out_size)
{
    const float* x        = (const float*)d_in[0];
    const float* Wq       = (const float*)d_in[1];
    const float* Wk       = (const float*)d_in[2];
    const float* Wv       = (const float*)d_in[3];
    const float* Wp       = (const float*)d_in[4];
    const float* bp       = (const float*)d_in[5];
    const float* rel_bias = (const float*)d_in[6];

    float* y_out = (float*)d_out;
    float* att   = (float*)d_out + Y_ELEMS;

    // K1: QKV GEMMs (z = 0:q, 1:k, 2:v)
    {
        dim3 grid(C_ / 128, ROWS_ / 128, 3);
        qkv_gemm_kernel<<<grid, 256>>>(x, Wq, Wk, Wv);
    }
    // K2: RoPE on q and k
    {
        dim3 grid((BH_ * T_) / 8, 2);
        rope_kernel<<<grid, 256>>>();
    }
    // K3: raw causal scores + bias
    {
        dim3 grid(T_ / 64, BH_);
        scores_kernel<<<grid, 256>>>(rel_bias, att);
    }
    // K4: row softmax (writes full att incl. zeros above diagonal)
    {
        softmax_kernel<<<BH_ * T_, 256>>>(att);
    }
    // K5: att @ v
    {
        dim3 grid(T_ / 64, BH_);
        av_kernel<<<grid, 256>>>(att);
    }
    // K6: output projection + bias
    {
        dim3 grid(C_ / 128, ROWS_ / 128);
        proj_kernel<<<grid, 256>>>(Wp, bp, y_out);
    }
}

// round 3
// speedup vs baseline: 3.0794x; 3.0794x over previous
#include <cuda_runtime.h>
#include <cuda_bf16.h>
#include <math.h>
#include <stdint.h>

// ---------------------------------------------------------------------------
// Problem constants
// ---------------------------------------------------------------------------
#define B_  2
#define T_  2048
#define C_  768
#define H_  12
#define D_  64
#define BH_ (B_*H_)            // 24
#define ROWS_ (B_*T_)          // 4096
#define QKV_ELEMS (BH_*T_*D_)  // 3,145,728
#define Y_ELEMS   (B_*T_*C_)
#define SCALE_ 0.125f
#define S_ 40                  // smem tile row stride (bf16 elems), mult of 8

// fp32 intermediates (device globals; no allocation allowed)
__device__ float g_q[QKV_ELEMS];    // [bh][t][d]
__device__ float g_k[QKV_ELEMS];    // [bh][t][d]
__device__ float g_vt[QKV_ELEMS];   // [bh][d][t]
__device__ float g_y[Y_ELEMS];      // [b*T+t][h*64+d]
__device__ float g_cosT[T_*32], g_sinT[T_*32];

// ---------------------------------------------------------------------------
// HMMA helpers (arch-agnostic: mma.sync + ldmatrix, valid on compute_103)
// ---------------------------------------------------------------------------
__device__ __forceinline__ void ldsm4(uint32_t* r, const __nv_bfloat16* p) {
    uint32_t a = (uint32_t)__cvta_generic_to_shared(p);
    asm volatile("ldmatrix.sync.aligned.m8n8.x4.shared.b16 {%0,%1,%2,%3}, [%4];"
        : "=r"(r[0]), "=r"(r[1]), "=r"(r[2]), "=r"(r[3]) : "r"(a));
}

__device__ __forceinline__ void mma_bf16(float* c, const uint32_t* a, const uint32_t* b) {
    asm volatile(
        "mma.sync.aligned.m16n8k16.row.col.f32.bf16.bf16.f32 "
        "{%0,%1,%2,%3}, {%4,%5,%6,%7}, {%8,%9}, {%0,%1,%2,%3};"
        : "+f"(c[0]), "+f"(c[1]), "+f"(c[2]), "+f"(c[3])
        : "r"(a[0]), "r"(a[1]), "r"(a[2]), "r"(a[3]), "r"(b[0]), "r"(b[1]));
}

// ---------------------------------------------------------------------------
// Tile movement: gmem fp32 -> regs -> (convert) -> smem bf16 hi/lo
// 128-row x 32-col tile, 256 threads: each thread 16 floats.
// ---------------------------------------------------------------------------
__device__ __forceinline__ void ld_t128(float4* r, const float* src, int stride, int tid) {
    const float* s = src + (size_t)(tid >> 1) * stride + ((tid & 1) << 4);
    #pragma unroll
    for (int v = 0; v < 4; v++) r[v] = ((const float4*)s)[v];
}
__device__ __forceinline__ void st_t128(const float4* r, __nv_bfloat16* hi,
                                        __nv_bfloat16* lo, int tid) {
    const int row = tid >> 1, c0 = (tid & 1) << 4;
    __nv_bfloat16* ph = hi + row * S_ + c0;
    __nv_bfloat16* pl = lo + row * S_ + c0;
    #pragma unroll
    for (int v = 0; v < 4; v++) {
        float4 f = r[v];
        __nv_bfloat162 h0 = __floats2bfloat162_rn(f.x, f.y);
        __nv_bfloat162 h1 = __floats2bfloat162_rn(f.z, f.w);
        __nv_bfloat162 l0 = __floats2bfloat162_rn(f.x - __bfloat162float(h0.x),
                                                  f.y - __bfloat162float(h0.y));
        __nv_bfloat162 l1 = __floats2bfloat162_rn(f.z - __bfloat162float(h1.x),
                                                  f.w - __bfloat162float(h1.y));
        ((__nv_bfloat162*)(ph + v * 4))[0] = h0;
        ((__nv_bfloat162*)(ph + v * 4))[1] = h1;
        ((__nv_bfloat162*)(pl + v * 4))[0] = l0;
        ((__nv_bfloat162*)(pl + v * 4))[1] = l1;
    }
}
// 64-row x 32-col tile, 256 threads: each thread 8 floats.
__device__ __forceinline__ void ld_t64(float4* r, const float* src, int stride, int tid) {
    const float* s = src + (size_t)(tid >> 2) * stride + ((tid & 3) << 3);
    r[0] = ((const float4*)s)[0];
    r[1] = ((const float4*)s)[1];
}
__device__ __forceinline__ void st_t64(const float4* r, __nv_bfloat16* hi,
                                       __nv_bfloat16* lo, int tid) {
    const int row = tid >> 2, c0 = (tid & 3) << 3;
    __nv_bfloat16* ph = hi + row * S_ + c0;
    __nv_bfloat16* pl = lo + row * S_ + c0;
    #pragma unroll
    for (int v = 0; v < 2; v++) {
        float4 f = r[v];
        __nv_bfloat162 h0 = __floats2bfloat162_rn(f.x, f.y);
        __nv_bfloat162 h1 = __floats2bfloat162_rn(f.z, f.w);
        __nv_bfloat162 l0 = __floats2bfloat162_rn(f.x - __bfloat162float(h0.x),
                                                  f.y - __bfloat162float(h0.y));
        __nv_bfloat162 l1 = __floats2bfloat162_rn(f.z - __bfloat162float(h1.x),
                                                  f.w - __bfloat162float(h1.y));
        ((__nv_bfloat162*)(ph + v * 4))[0] = h0;
        ((__nv_bfloat162*)(ph + v * 4))[1] = h1;
        ((__nv_bfloat162*)(pl + v * 4))[0] = l0;
        ((__nv_bfloat162*)(pl + v * 4))[1] = l1;
    }
}

// ---------------------------------------------------------------------------
// Core: one BK=32 chunk of split-bf16 MMA. Warp tile = 32(M) x (NF*8)(N).
// acc[mi*NF + nf][4]. 3 split terms: hi*hi + hi*lo + lo*hi.
// ---------------------------------------------------------------------------
template<int NF>
__device__ __forceinline__ void compute_chunk(
    const __nv_bfloat16* __restrict__ sAh, const __nv_bfloat16* __restrict__ sAl,
    const __nv_bfloat16* __restrict__ sBh, const __nv_bfloat16* __restrict__ sBl,
    int wm0, int wn0, int lane, float (*acc)[4])
{
    const int ar = lane & 15, acs = (lane >> 4) << 3;
    const int br = (lane & 7) + ((lane >> 4) << 3), bcs = ((lane >> 3) & 1) << 3;
    #pragma unroll
    for (int ks = 0; ks < 2; ks++) {
        const int k0 = ks << 4;
        uint32_t ah0[4], ah1[4], al0[4], al1[4];
        ldsm4(ah0, sAh + (wm0 + ar) * S_ + k0 + acs);
        ldsm4(ah1, sAh + (wm0 + 16 + ar) * S_ + k0 + acs);
        ldsm4(al0, sAl + (wm0 + ar) * S_ + k0 + acs);
        ldsm4(al1, sAl + (wm0 + 16 + ar) * S_ + k0 + acs);
        #pragma unroll
        for (int ng = 0; ng < NF / 2; ng++) {
            const int n0 = wn0 + (ng << 4);
            uint32_t bh[4], bl[4];
            ldsm4(bh, sBh + (n0 + br) * S_ + k0 + bcs);
            ldsm4(bl, sBl + (n0 + br) * S_ + k0 + bcs);
            #pragma unroll
            for (int mi = 0; mi < 2; mi++) {
                const uint32_t* am = mi ? ah1 : ah0;
                const uint32_t* alm = mi ? al1 : al0;
                float* cA = acc[mi * NF + ng * 2];
                float* cB = acc[mi * NF + ng * 2 + 1];
                mma_bf16(cA, am, bh);     mma_bf16(cA, am, bl);     mma_bf16(cA, alm, bh);
                mma_bf16(cB, am, bh + 2); mma_bf16(cB, am, bl + 2); mma_bf16(cB, alm, bh + 2);
            }
        }
    }
}

// ---------------------------------------------------------------------------
// K0: RoPE trig tables
// ---------------------------------------------------------------------------
__global__ __launch_bounds__(256) void trig_kernel()
{
    int idx = blockIdx.x * 256 + threadIdx.x;
    if (idx >= T_ * 32) return;
    int t = idx >> 5, j = idx & 31;
    const float inv = (float)pow(10000.0, -(double)j / 32.0);
    const float ang = (float)t * inv;
    g_cosT[idx] = cosf(ang);
    g_sinT[idx] = sinf(ang);
}

// ---------------------------------------------------------------------------
// K1: QKV projection (HMMA split-bf16). 128x128 tile, K=768.
//     Epilogue: RoPE for q,k; q,k -> [bh][t][d]; v -> [bh][d][t].
// ---------------------------------------------------------------------------
__global__ __launch_bounds__(256) void qkv_mma(
    const float* __restrict__ x, const float* __restrict__ Wq,
    const float* __restrict__ Wk, const float* __restrict__ Wv)
{
    __shared__ __nv_bfloat16 sAh[128*S_], sAl[128*S_], sBh[128*S_], sBl[128*S_];
    const int tid = threadIdx.x, lane = tid & 31, wid = tid >> 5;
    const int wm = wid & 3, wn = wid >> 2;
    const int z = blockIdx.z;
    const int row0 = blockIdx.y * 128, col0 = blockIdx.x * 128;
    const float* W = (z == 0) ? Wq : (z == 1) ? Wk : Wv;

    float acc[16][4];
    #pragma unroll
    for (int i = 0; i < 16; i++)
        #pragma unroll
        for (int j = 0; j < 4; j++) acc[i][j] = 0.0f;

    float4 ra[4], rb[4];
    ld_t128(ra, x + (size_t)row0 * C_, C_, tid);
    ld_t128(rb, W + (size_t)col0 * C_, C_, tid);
    for (int c = 0; c < 24; c++) {
        st_t128(ra, sAh, sAl, tid);
        st_t128(rb, sBh, sBl, tid);
        __syncthreads();
        if (c < 23) {
            ld_t128(ra, x + (size_t)row0 * C_ + (c + 1) * 32, C_, tid);
            ld_t128(rb, W + (size_t)col0 * C_ + (c + 1) * 32, C_, tid);
        }
        compute_chunk<8>(sAh, sAl, sBh, sBl, wm * 32, wn * 64, lane, acc);
        __syncthreads();
    }

    const int g = lane >> 2, tg2 = (lane & 3) << 1;
    const int rowB = row0 + wm * 32, colB = col0 + wn * 64;

    if (z < 2) {  // RoPE on first 32 dims of each head
        #pragma unroll
        for (int mi = 0; mi < 2; mi++)
            #pragma unroll
            for (int ci = 0; ci < 4; ci++) {
                const int row = rowB + mi * 16 + g + (ci >> 1) * 8;
                const int t = row & (T_ - 1);
                const int e = ci & 1;
                #pragma unroll
                for (int nf = 0; nf < 2; nf++) {
                    const int d0 = nf * 8 + tg2 + e;
                    const float c0 = g_cosT[t * 32 + d0],      s0 = g_sinT[t * 32 + d0];
                    const float c1 = g_cosT[t * 32 + d0 + 16], s1 = g_sinT[t * 32 + d0 + 16];
                    const float u0 = acc[mi * 8 + nf][ci];
                    const float u1 = acc[mi * 8 + nf + 2][ci];
                    acc[mi * 8 + nf][ci]     = u0 * c0 - u1 * s0;
                    acc[mi * 8 + nf + 2][ci] = fmaf(u1, c1, u0 * s1);
                }
            }
    }

    float* dst = (z == 0) ? g_q : g_k;
    #pragma unroll
    for (int mi = 0; mi < 2; mi++)
        #pragma unroll
        for (int half = 0; half < 2; half++) {
            const int row = rowB + mi * 16 + g + half * 8;
            const int b = row >> 11, t = row & (T_ - 1);
            #pragma unroll
            for (int nf = 0; nf < 8; nf++) {
                const int col = colB + nf * 8 + tg2;
                const int h = col >> 6, d = col & 63;
                const int bh = b * H_ + h;
                const float v0 = acc[mi * 8 + nf][half * 2];
                const float v1 = acc[mi * 8 + nf][half * 2 + 1];
                if (z == 2) {
                    g_vt[((size_t)(bh * D_ + d)) * T_ + t] = v0;
                    g_vt[((size_t)(bh * D_ + d + 1)) * T_ + t] = v1;
                } else {
                    *(float2*)(dst + ((size_t)bh * T_ + t) * D_ + d) = make_float2(v0, v1);
                }
            }
        }
}

// ---------------------------------------------------------------------------
// K2: causal scores (HMMA). Lower-tri 128x128 tiles, K=64.
//     Epilogue: scale + rel_bias + causal mask -> att fp32.
// ---------------------------------------------------------------------------
__global__ __launch_bounds__(256) void scores_mma(
    const float* __restrict__ rel_bias, float* __restrict__ att)
{
    __shared__ __nv_bfloat16 sAh[128*S_], sAl[128*S_], sBh[128*S_], sBl[128*S_];
    __shared__ float bias_s[256];
    const int tid = threadIdx.x, lane = tid & 31, wid = tid >> 5;
    const int wm = wid & 3, wn = wid >> 2;

    int p = blockIdx.x, qt = 0;
    while ((qt + 1) * (qt + 2) / 2 <= p) qt++;
    const int kt = p - qt * (qt + 1) / 2;
    const int bh = blockIdx.y, h = bh % H_;
    const int q0 = qt * 128, k0 = kt * 128;

    if (tid < 255)
        bias_s[tid] = rel_bias[(size_t)((q0 - k0) + tid - 127 + (T_ - 1)) * H_ + h];

    const float* qsrc = g_q + ((size_t)bh * T_ + q0) * D_;
    const float* ksrc = g_k + ((size_t)bh * T_ + k0) * D_;

    float acc[16][4];
    #pragma unroll
    for (int i = 0; i < 16; i++)
        #pragma unroll
        for (int j = 0; j < 4; j++) acc[i][j] = 0.0f;

    float4 ra[4], rb[4];
    ld_t128(ra, qsrc, D_, tid);
    ld_t128(rb, ksrc, D_, tid);
    for (int c = 0; c < 2; c++) {
        st_t128(ra, sAh, sAl, tid);
        st_t128(rb, sBh, sBl, tid);
        __syncthreads();
        if (c == 0) {
            ld_t128(ra, qsrc + 32, D_, tid);
            ld_t128(rb, ksrc + 32, D_, tid);
        }
        compute_chunk<8>(sAh, sAl, sBh, sBl, wm * 32, wn * 64, lane, acc);
        __syncthreads();
    }

    const int g = lane >> 2, tg2 = (lane & 3) << 1;
    #pragma unroll
    for (int mi = 0; mi < 2; mi++)
        #pragma unroll
        for (int half = 0; half < 2; half++) {
            const int qi = q0 + wm * 32 + mi * 16 + g + half * 8;
            #pragma unroll
            for (int nf = 0; nf < 8; nf++) {
                const int ki = k0 + wn * 64 + nf * 8 + tg2;
                const int dd = qi - ki - q0 + k0 + 127;
                const float v0 = (ki <= qi)
                    ? fmaf(acc[mi * 8 + nf][half * 2], SCALE_, bias_s[dd]) : -1e30f;
                const float v1 = (ki + 1 <= qi)
                    ? fmaf(acc[mi * 8 + nf][half * 2 + 1], SCALE_, bias_s[dd - 1]) : -1e30f;
                *(float2*)(att + ((size_t)bh * T_ + qi) * T_ + ki) = make_float2(v0, v1);
            }
        }
}

// ---------------------------------------------------------------------------
// K3: row softmax over causal prefix; zeros above diagonal.
// ---------------------------------------------------------------------------
__global__ __launch_bounds__(256) void softmax_kernel(float* __restrict__ att)
{
    const int row = blockIdx.x;
    const int q = row & (T_ - 1);
    const int len = q + 1;
    float* p = att + (size_t)row * T_;

    __shared__ float buf[T_];
    __shared__ float red[256];
    const int tid = threadIdx.x;

    float m = -1e30f;
    for (int i = tid; i < len; i += 256) {
        const float v = p[i];
        buf[i] = v;
        m = fmaxf(m, v);
    }
    red[tid] = m;
    __syncthreads();
    #pragma unroll
    for (int s = 128; s > 0; s >>= 1) {
        if (tid < s) red[tid] = fmaxf(red[tid], red[tid + s]);
        __syncthreads();
    }
    m = red[0];
    __syncthreads();

    float sum = 0.0f;
    for (int i = tid; i < len; i += 256) {
        const float e = expf(buf[i] - m);
        buf[i] = e;
        sum += e;
    }
    red[tid] = sum;
    __syncthreads();
    #pragma unroll
    for (int s = 128; s > 0; s >>= 1) {
        if (tid < s) red[tid] += red[tid + s];
        __syncthreads();
    }
    const float inv = 1.0f / red[0];
    __syncthreads();

    for (int i = tid; i < T_; i += 256)
        p[i] = (i < len) ? buf[i] * inv : 0.0f;
}

// ---------------------------------------------------------------------------
// K4: y = att @ v (HMMA). Block 128(q) x 64(d); causal K range.
// ---------------------------------------------------------------------------
__global__ __launch_bounds__(256) void av_mma(const float* __restrict__ att)
{
    __shared__ __nv_bfloat16 sAh[128*S_], sAl[128*S_], sBh[64*S_], sBl[64*S_];
    const int tid = threadIdx.x, lane = tid & 31, wid = tid >> 5;
    const int wm = wid & 3, wn = wid >> 2;
    const int qt = blockIdx.x, bh = blockIdx.y;
    const int q0 = qt * 128;
    const int nch = 4 * (qt + 1);

    const float* asrc = att + ((size_t)bh * T_ + q0) * T_;
    const float* bsrc = g_vt + (size_t)bh * D_ * T_;

    float acc[8][4];
    #pragma unroll
    for (int i = 0; i < 8; i++)
        #pragma unroll
        for (int j = 0; j < 4; j++) acc[i][j] = 0.0f;

    float4 ra[4], rb[2];
    ld_t128(ra, asrc, T_, tid);
    ld_t64(rb, bsrc, T_, tid);
    for (int c = 0; c < nch; c++) {
        st_t128(ra, sAh, sAl, tid);
        st_t64(rb, sBh, sBl, tid);
        __syncthreads();
        if (c + 1 < nch) {
            ld_t128(ra, asrc + (c + 1) * 32, T_, tid);
            ld_t64(rb, bsrc + (c + 1) * 32, T_, tid);
        }
        compute_chunk<4>(sAh, sAl, sBh, sBl, wm * 32, wn * 32, lane, acc);
        __syncthreads();
    }

    const int g = lane >> 2, tg2 = (lane & 3) << 1;
    const int b = bh / H_, h = bh % H_;
    #pragma unroll
    for (int mi = 0; mi < 2; mi++)
        #pragma unroll
        for (int half = 0; half < 2; half++) {
            const int t = q0 + wm * 32 + mi * 16 + g + half * 8;
            #pragma unroll
            for (int nf = 0; nf < 4; nf++) {
                const int d = wn * 32 + nf * 8 + tg2;
                *(float2*)(g_y + ((size_t)(b * T_ + t)) * C_ + h * D_ + d) =
                    make_float2(acc[mi * 4 + nf][half * 2], acc[mi * 4 + nf][half * 2 + 1]);
            }
        }
}

// ---------------------------------------------------------------------------
// K5: output projection (HMMA) + bias.
// ---------------------------------------------------------------------------
__global__ __launch_bounds__(256) void proj_mma(
    const float* __restrict__ Wp, const float* __restrict__ bp,
    float* __restrict__ out)
{
    __shared__ __nv_bfloat16 sAh[128*S_], sAl[128*S_], sBh[128*S_], sBl[128*S_];
    const int tid = threadIdx.x, lane = tid & 31, wid = tid >> 5;
    const int wm = wid & 3, wn = wid >> 2;
    const int row0 = blockIdx.y * 128, col0 = blockIdx.x * 128;

    float acc[16][4];
    #pragma unroll
    for (int i = 0; i < 16; i++)
        #pragma unroll
        for (int j = 0; j < 4; j++) acc[i][j] = 0.0f;

    float4 ra[4], rb[4];
    ld_t128(ra, g_y + (size_t)row0 * C_, C_, tid);
    ld_t128(rb, Wp + (size_t)col0 * C_, C_, tid);
    for (int c = 0; c < 24; c++) {
        st_t128(ra, sAh, sAl, tid);
        st_t128(rb, sBh, sBl, tid);
        __syncthreads();
        if (c < 23) {
            ld_t128(ra, g_y + (size_t)row0 * C_ + (c + 1) * 32, C_, tid);
            ld_t128(rb, Wp + (size_t)col0 * C_ + (c + 1) * 32, C_, tid);
        }
        compute_chunk<8>(sAh, sAl, sBh, sBl, wm * 32, wn * 64, lane, acc);
        __syncthreads();
    }

    const int g = lane >> 2, tg2 = (lane & 3) << 1;
    #pragma unroll
    for (int mi = 0; mi < 2; mi++)
        #pragma unroll
        for (int half = 0; half < 2; half++) {
            const int row = row0 + wm * 32 + mi * 16 + g + half * 8;
            #pragma unroll
            for (int nf = 0; nf < 8; nf++) {
                const int col = col0 + wn * 64 + nf * 8 + tg2;
                const float v0 = acc[mi * 8 + nf][half * 2] + __ldg(&bp[col]);
                const float v1 = acc[mi * 8 + nf][half * 2 + 1] + __ldg(&bp[col + 1]);
                *(float2*)(out + (size_t)row * C_ + col) = make_float2(v0, v1);
            }
        }
}

// ---------------------------------------------------------------------------
// Launch
// ---------------------------------------------------------------------------
extern "C" void kernel_launch(void* const* d_in, const int* in_sizes, int n_in,
                              void* d_out, int out_size)
{
    const float* x        = (const float*)d_in[0];
    const float* Wq       = (const float*)d_in[1];
    const float* Wk       = (const float*)d_in[2];
    const float* Wv       = (const float*)d_in[3];
    const float* Wp       = (const float*)d_in[4];
    const float* bp       = (const float*)d_in[5];
    const float* rel_bias = (const float*)d_in[6];

    float* y_out = (float*)d_out;
    float* att   = (float*)d_out + Y_ELEMS;

    trig_kernel<<<(T_ * 32 + 255) / 256, 256>>>();
    qkv_mma<<<dim3(C_ / 128, ROWS_ / 128, 3), 256>>>(x, Wq, Wk, Wv);
    scores_mma<<<dim3(136, BH_), 256>>>(rel_bias, att);
    softmax_kernel<<<BH_ * T_, 256>>>(att);
    av_mma<<<dim3(T_ / 128, BH_), 256>>>(att);
    proj_mma<<<dim3(C_ / 128, ROWS_ / 128), 256>>>(Wp, bp, y_out);
}

// round 4
// speedup vs baseline: 3.1256x; 1.0150x over previous
#include <cuda_runtime.h>
#include <cuda_bf16.h>
#include <math.h>
#include <stdint.h>

// ---------------------------------------------------------------------------
// Problem constants
// ---------------------------------------------------------------------------
#define B_  2
#define T_  2048
#define C_  768
#define H_  12
#define D_  64
#define BH_ (B_*H_)            // 24
#define ROWS_ (B_*T_)          // 4096
#define QKV_ELEMS (BH_*T_*D_)  // 3,145,728
#define Y_ELEMS   (B_*T_*C_)
#define SCALE_ 0.125f
#define S_ 40                  // smem tile row stride (bf16 elems), mult of 8

// Stage layouts (bf16 element offsets within one stage)
#define TILE_ (128*S_)                 // 5120
#define BIG_AH  0
#define BIG_AL  TILE_
#define BIG_BH  (2*TILE_)
#define BIG_BL  (3*TILE_)
#define BIG_STAGE (4*TILE_)            // 20480 elems = 40960 B
#define BIG_SMEM  (2*BIG_STAGE*2)      // bytes: 81920

#define AV_AH  0
#define AV_AL  TILE_
#define AV_BH  (2*TILE_)
#define AV_BL  (2*TILE_ + 64*S_)
#define AV_STAGE (2*TILE_ + 2*64*S_)   // 15360 elems = 30720 B
#define AV_SMEM  (2*AV_STAGE*2)        // bytes: 61440

// fp32 intermediates (device globals; no allocation allowed)
__device__ float g_q[QKV_ELEMS];    // [bh][t][d]
__device__ float g_k[QKV_ELEMS];    // [bh][t][d]
__device__ float g_vt[QKV_ELEMS];   // [bh][d][t]
__device__ float g_y[Y_ELEMS];      // [b*T+t][h*64+d]
__device__ float g_cosT[T_*32], g_sinT[T_*32];

// ---------------------------------------------------------------------------
// HMMA helpers (arch-agnostic: mma.sync + ldmatrix, valid on compute_103)
// ---------------------------------------------------------------------------
__device__ __forceinline__ void ldsm4(uint32_t* r, const __nv_bfloat16* p) {
    uint32_t a = (uint32_t)__cvta_generic_to_shared(p);
    asm volatile("ldmatrix.sync.aligned.m8n8.x4.shared.b16 {%0,%1,%2,%3}, [%4];"
        : "=r"(r[0]), "=r"(r[1]), "=r"(r[2]), "=r"(r[3]) : "r"(a));
}

__device__ __forceinline__ void mma_bf16(float* c, const uint32_t* a, const uint32_t* b) {
    asm volatile(
        "mma.sync.aligned.m16n8k16.row.col.f32.bf16.bf16.f32 "
        "{%0,%1,%2,%3}, {%4,%5,%6,%7}, {%8,%9}, {%0,%1,%2,%3};"
        : "+f"(c[0]), "+f"(c[1]), "+f"(c[2]), "+f"(c[3])
        : "r"(a[0]), "r"(a[1]), "r"(a[2]), "r"(a[3]), "r"(b[0]), "r"(b[1]));
}

// ---------------------------------------------------------------------------
// Tile movement: gmem fp32 -> regs -> (convert) -> smem bf16 hi/lo
// ---------------------------------------------------------------------------
__device__ __forceinline__ void ld_t128(float4* r, const float* src, int stride, int tid) {
    const float* s = src + (size_t)(tid >> 1) * stride + ((tid & 1) << 4);
    #pragma unroll
    for (int v = 0; v < 4; v++) r[v] = ((const float4*)s)[v];
}
__device__ __forceinline__ void st_t128(const float4* r, __nv_bfloat16* hi,
                                        __nv_bfloat16* lo, int tid) {
    const int row = tid >> 1, c0 = (tid & 1) << 4;
    __nv_bfloat16* ph = hi + row * S_ + c0;
    __nv_bfloat16* pl = lo + row * S_ + c0;
    #pragma unroll
    for (int v = 0; v < 4; v++) {
        float4 f = r[v];
        __nv_bfloat162 h0 = __floats2bfloat162_rn(f.x, f.y);
        __nv_bfloat162 h1 = __floats2bfloat162_rn(f.z, f.w);
        __nv_bfloat162 l0 = __floats2bfloat162_rn(f.x - __bfloat162float(h0.x),
                                                  f.y - __bfloat162float(h0.y));
        __nv_bfloat162 l1 = __floats2bfloat162_rn(f.z - __bfloat162float(h1.x),
                                                  f.w - __bfloat162float(h1.y));
        ((__nv_bfloat162*)(ph + v * 4))[0] = h0;
        ((__nv_bfloat162*)(ph + v * 4))[1] = h1;
        ((__nv_bfloat162*)(pl + v * 4))[0] = l0;
        ((__nv_bfloat162*)(pl + v * 4))[1] = l1;
    }
}
__device__ __forceinline__ void ld_t64(float4* r, const float* src, int stride, int tid) {
    const float* s = src + (size_t)(tid >> 2) * stride + ((tid & 3) << 3);
    r[0] = ((const float4*)s)[0];
    r[1] = ((const float4*)s)[1];
}
__device__ __forceinline__ void st_t64(const float4* r, __nv_bfloat16* hi,
                                       __nv_bfloat16* lo, int tid) {
    const int row = tid >> 2, c0 = (tid & 3) << 3;
    __nv_bfloat16* ph = hi + row * S_ + c0;
    __nv_bfloat16* pl = lo + row * S_ + c0;
    #pragma unroll
    for (int v = 0; v < 2; v++) {
        float4 f = r[v];
        __nv_bfloat162 h0 = __floats2bfloat162_rn(f.x, f.y);
        __nv_bfloat162 h1 = __floats2bfloat162_rn(f.z, f.w);
        __nv_bfloat162 l0 = __floats2bfloat162_rn(f.x - __bfloat162float(h0.x),
                                                  f.y - __bfloat162float(h0.y));
        __nv_bfloat162 l1 = __floats2bfloat162_rn(f.z - __bfloat162float(h1.x),
                                                  f.w - __bfloat162float(h1.y));
        ((__nv_bfloat162*)(ph + v * 4))[0] = h0;
        ((__nv_bfloat162*)(ph + v * 4))[1] = h1;
        ((__nv_bfloat162*)(pl + v * 4))[0] = l0;
        ((__nv_bfloat162*)(pl + v * 4))[1] = l1;
    }
}

// ---------------------------------------------------------------------------
// Core: one BK=32 chunk of split-bf16 MMA. Warp tile = 32(M) x (NF*8)(N).
// 3 split terms: hi*hi + hi*lo + lo*hi.
// ---------------------------------------------------------------------------
template<int NF>
__device__ __forceinline__ void compute_chunk(
    const __nv_bfloat16* __restrict__ sAh, const __nv_bfloat16* __restrict__ sAl,
    const __nv_bfloat16* __restrict__ sBh, const __nv_bfloat16* __restrict__ sBl,
    int wm0, int wn0, int lane, float (*acc)[4])
{
    const int ar = lane & 15, acs = (lane >> 4) << 3;
    const int br = (lane & 7) + ((lane >> 4) << 3), bcs = ((lane >> 3) & 1) << 3;
    #pragma unroll
    for (int ks = 0; ks < 2; ks++) {
        const int k0 = ks << 4;
        uint32_t ah0[4], ah1[4], al0[4], al1[4];
        ldsm4(ah0, sAh + (wm0 + ar) * S_ + k0 + acs);
        ldsm4(ah1, sAh + (wm0 + 16 + ar) * S_ + k0 + acs);
        ldsm4(al0, sAl + (wm0 + ar) * S_ + k0 + acs);
        ldsm4(al1, sAl + (wm0 + 16 + ar) * S_ + k0 + acs);
        #pragma unroll
        for (int ng = 0; ng < NF / 2; ng++) {
            const int n0 = wn0 + (ng << 4);
            uint32_t bh[4], bl[4];
            ldsm4(bh, sBh + (n0 + br) * S_ + k0 + bcs);
            ldsm4(bl, sBl + (n0 + br) * S_ + k0 + bcs);
            #pragma unroll
            for (int mi = 0; mi < 2; mi++) {
                const uint32_t* am = mi ? ah1 : ah0;
                const uint32_t* alm = mi ? al1 : al0;
                float* cA = acc[mi * NF + ng * 2];
                float* cB = acc[mi * NF + ng * 2 + 1];
                mma_bf16(cA, am, bh);     mma_bf16(cA, am, bl);     mma_bf16(cA, alm, bh);
                mma_bf16(cB, am, bh + 2); mma_bf16(cB, am, bl + 2); mma_bf16(cB, alm, bh + 2);
            }
        }
    }
}

// ---------------------------------------------------------------------------
// K0: RoPE trig tables
// ---------------------------------------------------------------------------
__global__ __launch_bounds__(256) void trig_kernel()
{
    int idx = blockIdx.x * 256 + threadIdx.x;
    if (idx >= T_ * 32) return;
    int t = idx >> 5, j = idx & 31;
    const float inv = (float)pow(10000.0, -(double)j / 32.0);
    const float ang = (float)t * inv;
    g_cosT[idx] = cosf(ang);
    g_sinT[idx] = sinf(ang);
}

// ---------------------------------------------------------------------------
// K1: QKV projection. Double-buffered smem, 128x128 tile, K=768.
// ---------------------------------------------------------------------------
__global__ __launch_bounds__(256) void qkv_mma(
    const float* __restrict__ x, const float* __restrict__ Wq,
    const float* __restrict__ Wk, const float* __restrict__ Wv)
{
    extern __shared__ __align__(16) __nv_bfloat16 sm[];
    const int tid = threadIdx.x, lane = tid & 31, wid = tid >> 5;
    const int wm = wid & 3, wn = wid >> 2;
    const int z = blockIdx.z;
    const int row0 = blockIdx.y * 128, col0 = blockIdx.x * 128;
    const float* W = (z == 0) ? Wq : (z == 1) ? Wk : Wv;
    const float* Asrc = x + (size_t)row0 * C_;
    const float* Bsrc = W + (size_t)col0 * C_;

    float acc[16][4];
    #pragma unroll
    for (int i = 0; i < 16; i++)
        #pragma unroll
        for (int j = 0; j < 4; j++) acc[i][j] = 0.0f;

    const int nch = 24;
    float4 ra[4], rb[4];
    ld_t128(ra, Asrc, C_, tid);
    ld_t128(rb, Bsrc, C_, tid);
    st_t128(ra, sm + BIG_AH, sm + BIG_AL, tid);
    st_t128(rb, sm + BIG_BH, sm + BIG_BL, tid);
    ld_t128(ra, Asrc + 32, C_, tid);
    ld_t128(rb, Bsrc + 32, C_, tid);
    __syncthreads();

    for (int c = 0; c < nch; c++) {
        __nv_bfloat16* cur = sm + (c & 1) * BIG_STAGE;
        if (c + 1 < nch) {
            __nv_bfloat16* nxt = sm + ((c + 1) & 1) * BIG_STAGE;
            st_t128(ra, nxt + BIG_AH, nxt + BIG_AL, tid);
            st_t128(rb, nxt + BIG_BH, nxt + BIG_BL, tid);
        }
        if (c + 2 < nch) {
            ld_t128(ra, Asrc + (c + 2) * 32, C_, tid);
            ld_t128(rb, Bsrc + (c + 2) * 32, C_, tid);
        }
        compute_chunk<8>(cur + BIG_AH, cur + BIG_AL, cur + BIG_BH, cur + BIG_BL,
                         wm * 32, wn * 64, lane, acc);
        __syncthreads();
    }

    const int g = lane >> 2, tg2 = (lane & 3) << 1;
    const int rowB = row0 + wm * 32, colB = col0 + wn * 64;

    if (z < 2) {  // RoPE on first 32 dims of each head
        #pragma unroll
        for (int mi = 0; mi < 2; mi++)
            #pragma unroll
            for (int ci = 0; ci < 4; ci++) {
                const int row = rowB + mi * 16 + g + (ci >> 1) * 8;
                const int t = row & (T_ - 1);
                const int e = ci & 1;
                #pragma unroll
                for (int nf = 0; nf < 2; nf++) {
                    const int d0 = nf * 8 + tg2 + e;
                    const float c0 = g_cosT[t * 32 + d0],      s0 = g_sinT[t * 32 + d0];
                    const float c1 = g_cosT[t * 32 + d0 + 16], s1 = g_sinT[t * 32 + d0 + 16];
                    const float u0 = acc[mi * 8 + nf][ci];
                    const float u1 = acc[mi * 8 + nf + 2][ci];
                    acc[mi * 8 + nf][ci]     = u0 * c0 - u1 * s0;
                    acc[mi * 8 + nf + 2][ci] = fmaf(u1, c1, u0 * s1);
                }
            }
    }

    float* dst = (z == 0) ? g_q : g_k;
    #pragma unroll
    for (int mi = 0; mi < 2; mi++)
        #pragma unroll
        for (int half = 0; half < 2; half++) {
            const int row = rowB + mi * 16 + g + half * 8;
            const int b = row >> 11, t = row & (T_ - 1);
            #pragma unroll
            for (int nf = 0; nf < 8; nf++) {
                const int col = colB + nf * 8 + tg2;
                const int h = col >> 6, d = col & 63;
                const int bh = b * H_ + h;
                const float v0 = acc[mi * 8 + nf][half * 2];
                const float v1 = acc[mi * 8 + nf][half * 2 + 1];
                if (z == 2) {
                    g_vt[((size_t)(bh * D_ + d)) * T_ + t] = v0;
                    g_vt[((size_t)(bh * D_ + d + 1)) * T_ + t] = v1;
                } else {
                    *(float2*)(dst + ((size_t)bh * T_ + t) * D_ + d) = make_float2(v0, v1);
                }
            }
        }
}

// ---------------------------------------------------------------------------
// K2: causal scores. Lower-tri 128x128 tiles, K=64 (2 chunks, double-buffered).
// ---------------------------------------------------------------------------
__global__ __launch_bounds__(256) void scores_mma(
    const float* __restrict__ rel_bias, float* __restrict__ att)
{
    extern __shared__ __align__(16) __nv_bfloat16 sm[];
    __shared__ float bias_s[256];
    const int tid = threadIdx.x, lane = tid & 31, wid = tid >> 5;
    const int wm = wid & 3, wn = wid >> 2;

    int p = blockIdx.x, qt = 0;
    while ((qt + 1) * (qt + 2) / 2 <= p) qt++;
    const int kt = p - qt * (qt + 1) / 2;
    const int bh = blockIdx.y, h = bh % H_;
    const int q0 = qt * 128, k0 = kt * 128;

    if (tid < 255)
        bias_s[tid] = rel_bias[(size_t)((q0 - k0) + tid - 127 + (T_ - 1)) * H_ + h];

    const float* qsrc = g_q + ((size_t)bh * T_ + q0) * D_;
    const float* ksrc = g_k + ((size_t)bh * T_ + k0) * D_;

    float acc[16][4];
    #pragma unroll
    for (int i = 0; i < 16; i++)
        #pragma unroll
        for (int j = 0; j < 4; j++) acc[i][j] = 0.0f;

    float4 ra[4], rb[4];
    ld_t128(ra, qsrc, D_, tid);
    ld_t128(rb, ksrc, D_, tid);
    st_t128(ra, sm + BIG_AH, sm + BIG_AL, tid);
    st_t128(rb, sm + BIG_BH, sm + BIG_BL, tid);
    ld_t128(ra, qsrc + 32, D_, tid);
    ld_t128(rb, ksrc + 32, D_, tid);
    __syncthreads();

    for (int c = 0; c < 2; c++) {
        __nv_bfloat16* cur = sm + (c & 1) * BIG_STAGE;
        if (c == 0) {
            __nv_bfloat16* nxt = sm + BIG_STAGE;
            st_t128(ra, nxt + BIG_AH, nxt + BIG_AL, tid);
            st_t128(rb, nxt + BIG_BH, nxt + BIG_BL, tid);
        }
        compute_chunk<8>(cur + BIG_AH, cur + BIG_AL, cur + BIG_BH, cur + BIG_BL,
                         wm * 32, wn * 64, lane, acc);
        __syncthreads();
    }

    const int g = lane >> 2, tg2 = (lane & 3) << 1;
    #pragma unroll
    for (int mi = 0; mi < 2; mi++)
        #pragma unroll
        for (int half = 0; half < 2; half++) {
            const int qi = q0 + wm * 32 + mi * 16 + g + half * 8;
            #pragma unroll
            for (int nf = 0; nf < 8; nf++) {
                const int ki = k0 + wn * 64 + nf * 8 + tg2;
                const int dd = qi - ki - q0 + k0 + 127;
                const float v0 = (ki <= qi)
                    ? fmaf(acc[mi * 8 + nf][half * 2], SCALE_, bias_s[dd]) : -1e30f;
                const float v1 = (ki + 1 <= qi)
                    ? fmaf(acc[mi * 8 + nf][half * 2 + 1], SCALE_, bias_s[dd - 1]) : -1e30f;
                *(float2*)(att + ((size_t)bh * T_ + qi) * T_ + ki) = make_float2(v0, v1);
            }
        }
}

// ---------------------------------------------------------------------------
// K3: row softmax — branch-free float4 streaming over [0, kend), zero tail.
//     Raw scores beyond the causal boundary are -1e30 -> exp -> 0.
// ---------------------------------------------------------------------------
__global__ __launch_bounds__(256) void softmax_kernel(float* __restrict__ att)
{
    const int row = blockIdx.x;
    const int q = row & (T_ - 1);
    const int n4 = (((q >> 7) + 1) << 7) >> 2;   // kend/4, 32..512
    float4* p4 = (float4*)(att + (size_t)row * T_);

    __shared__ float4 buf[T_/4];
    __shared__ float smax[8], ssum[8];
    const int tid = threadIdx.x, lane = tid & 31, wrp = tid >> 5;

    float m = -1e30f;
    for (int i = tid; i < n4; i += 256) {
        const float4 f = p4[i];
        buf[i] = f;
        m = fmaxf(fmaxf(m, fmaxf(f.x, f.y)), fmaxf(f.z, f.w));
    }
    #pragma unroll
    for (int o = 16; o > 0; o >>= 1)
        m = fmaxf(m, __shfl_xor_sync(0xffffffffu, m, o));
    if (lane == 0) smax[wrp] = m;
    __syncthreads();
    m = smax[0];
    #pragma unroll
    for (int w = 1; w < 8; w++) m = fmaxf(m, smax[w]);

    float sum = 0.0f;
    for (int i = tid; i < n4; i += 256) {
        float4 f = buf[i];
        f.x = __expf(f.x - m); f.y = __expf(f.y - m);
        f.z = __expf(f.z - m); f.w = __expf(f.w - m);
        buf[i] = f;
        sum += (f.x + f.y) + (f.z + f.w);
    }
    #pragma unroll
    for (int o = 16; o > 0; o >>= 1)
        sum += __shfl_xor_sync(0xffffffffu, sum, o);
    if (lane == 0) ssum[wrp] = sum;
    __syncthreads();
    sum = ssum[0];
    #pragma unroll
    for (int w = 1; w < 8; w++) sum += ssum[w];
    const float inv = 1.0f / sum;

    for (int i = tid; i < n4; i += 256) {
        float4 f = buf[i];
        f.x *= inv; f.y *= inv; f.z *= inv; f.w *= inv;
        p4[i] = f;
    }
    const float4 z4 = make_float4(0.f, 0.f, 0.f, 0.f);
    for (int i = n4 + tid; i < T_/4; i += 256)
        p4[i] = z4;
}

// ---------------------------------------------------------------------------
// K4: y = att @ v. Double-buffered; block 128(q) x 64(d); causal K range.
// ---------------------------------------------------------------------------
__global__ __launch_bounds__(256) void av_mma(const float* __restrict__ att)
{
    extern __shared__ __align__(16) __nv_bfloat16 sm[];
    const int tid = threadIdx.x, lane = tid & 31, wid = tid >> 5;
    const int wm = wid & 3, wn = wid >> 2;
    const int qt = blockIdx.x, bh = blockIdx.y;
    const int q0 = qt * 128;
    const int nch = 4 * (qt + 1);

    const float* asrc = att + ((size_t)bh * T_ + q0) * T_;
    const float* bsrc = g_vt + (size_t)bh * D_ * T_;

    float acc[8][4];
    #pragma unroll
    for (int i = 0; i < 8; i++)
        #pragma unroll
        for (int j = 0; j < 4; j++) acc[i][j] = 0.0f;

    float4 ra[4], rb[2];
    ld_t128(ra, asrc, T_, tid);
    ld_t64(rb, bsrc, T_, tid);
    st_t128(ra, sm + AV_AH, sm + AV_AL, tid);
    st_t64(rb, sm + AV_BH, sm + AV_BL, tid);
    if (nch > 1) {
        ld_t128(ra, asrc + 32, T_, tid);
        ld_t64(rb, bsrc + 32, T_, tid);
    }
    __syncthreads();

    for (int c = 0; c < nch; c++) {
        __nv_bfloat16* cur = sm + (c & 1) * AV_STAGE;
        if (c + 1 < nch) {
            __nv_bfloat16* nxt = sm + ((c + 1) & 1) * AV_STAGE;
            st_t128(ra, nxt + AV_AH, nxt + AV_AL, tid);
            st_t64(rb, nxt + AV_BH, nxt + AV_BL, tid);
        }
        if (c + 2 < nch) {
            ld_t128(ra, asrc + (c + 2) * 32, T_, tid);
            ld_t64(rb, bsrc + (c + 2) * 32, T_, tid);
        }
        compute_chunk<4>(cur + AV_AH, cur + AV_AL, cur + AV_BH, cur + AV_BL,
                         wm * 32, wn * 32, lane, acc);
        __syncthreads();
    }

    const int g = lane >> 2, tg2 = (lane & 3) << 1;
    const int b = bh / H_, h = bh % H_;
    #pragma unroll
    for (int mi = 0; mi < 2; mi++)
        #pragma unroll
        for (int half = 0; half < 2; half++) {
            const int t = q0 + wm * 32 + mi * 16 + g + half * 8;
            #pragma unroll
            for (int nf = 0; nf < 4; nf++) {
                const int d = wn * 32 + nf * 8 + tg2;
                *(float2*)(g_y + ((size_t)(b * T_ + t)) * C_ + h * D_ + d) =
                    make_float2(acc[mi * 4 + nf][half * 2], acc[mi * 4 + nf][half * 2 + 1]);
            }
        }
}

// ---------------------------------------------------------------------------
// K5: output projection + bias. Double-buffered.
// ---------------------------------------------------------------------------
__global__ __launch_bounds__(256) void proj_mma(
    const float* __restrict__ Wp, const float* __restrict__ bp,
    float* __restrict__ out)
{
    extern __shared__ __align__(16) __nv_bfloat16 sm[];
    const int tid = threadIdx.x, lane = tid & 31, wid = tid >> 5;
    const int wm = wid & 3, wn = wid >> 2;
    const int row0 = blockIdx.y * 128, col0 = blockIdx.x * 128;
    const float* Asrc = g_y + (size_t)row0 * C_;
    const float* Bsrc = Wp + (size_t)col0 * C_;

    float acc[16][4];
    #pragma unroll
    for (int i = 0; i < 16; i++)
        #pragma unroll
        for (int j = 0; j < 4; j++) acc[i][j] = 0.0f;

    const int nch = 24;
    float4 ra[4], rb[4];
    ld_t128(ra, Asrc, C_, tid);
    ld_t128(rb, Bsrc, C_, tid);
    st_t128(ra, sm + BIG_AH, sm + BIG_AL, tid);
    st_t128(rb, sm + BIG_BH, sm + BIG_BL, tid);
    ld_t128(ra, Asrc + 32, C_, tid);
    ld_t128(rb, Bsrc + 32, C_, tid);
    __syncthreads();

    for (int c = 0; c < nch; c++) {
        __nv_bfloat16* cur = sm + (c & 1) * BIG_STAGE;
        if (c + 1 < nch) {
            __nv_bfloat16* nxt = sm + ((c + 1) & 1) * BIG_STAGE;
            st_t128(ra, nxt + BIG_AH, nxt + BIG_AL, tid);
            st_t128(rb, nxt + BIG_BH, nxt + BIG_BL, tid);
        }
        if (c + 2 < nch) {
            ld_t128(ra, Asrc + (c + 2) * 32, C_, tid);
            ld_t128(rb, Bsrc + (c + 2) * 32, C_, tid);
        }
        compute_chunk<8>(cur + BIG_AH, cur + BIG_AL, cur + BIG_BH, cur + BIG_BL,
                         wm * 32, wn * 64, lane, acc);
        __syncthreads();
    }

    const int g = lane >> 2, tg2 = (lane & 3) << 1;
    #pragma unroll
    for (int mi = 0; mi < 2; mi++)
        #pragma unroll
        for (int half = 0; half < 2; half++) {
            const int row = row0 + wm * 32 + mi * 16 + g + half * 8;
            #pragma unroll
            for (int nf = 0; nf < 8; nf++) {
                const int col = col0 + wn * 64 + nf * 8 + tg2;
                const float v0 = acc[mi * 8 + nf][half * 2] + __ldg(&bp[col]);
                const float v1 = acc[mi * 8 + nf][half * 2 + 1] + __ldg(&bp[col + 1]);
                *(float2*)(out + (size_t)row * C_ + col) = make_float2(v0, v1);
            }
        }
}

// ---------------------------------------------------------------------------
// Launch
// ---------------------------------------------------------------------------
extern "C" void kernel_launch(void* const* d_in, const int* in_sizes, int n_in,
                              void* d_out, int out_size)
{
    const float* x        = (const float*)d_in[0];
    const float* Wq       = (const float*)d_in[1];
    const float* Wk       = (const float*)d_in[2];
    const float* Wv       = (const float*)d_in[3];
    const float* Wp       = (const float*)d_in[4];
    const float* bp       = (const float*)d_in[5];
    const float* rel_bias = (const float*)d_in[6];

    float* y_out = (float*)d_out;
    float* att   = (float*)d_out + Y_ELEMS;

    cudaFuncSetAttribute(qkv_mma,    cudaFuncAttributeMaxDynamicSharedMemorySize, BIG_SMEM);
    cudaFuncSetAttribute(scores_mma, cudaFuncAttributeMaxDynamicSharedMemorySize, BIG_SMEM);
    cudaFuncSetAttribute(av_mma,     cudaFuncAttributeMaxDynamicSharedMemorySize, AV_SMEM);
    cudaFuncSetAttribute(proj_mma,   cudaFuncAttributeMaxDynamicSharedMemorySize, BIG_SMEM);

    trig_kernel<<<(T_ * 32 + 255) / 256, 256>>>();
    qkv_mma<<<dim3(C_ / 128, ROWS_ / 128, 3), 256, BIG_SMEM>>>(x, Wq, Wk, Wv);
    scores_mma<<<dim3(136, BH_), 256, BIG_SMEM>>>(rel_bias, att);
    softmax_kernel<<<BH_ * T_, 256>>>(att);
    av_mma<<<dim3(T_ / 128, BH_), 256, AV_SMEM>>>(att);
    proj_mma<<<dim3(C_ / 128, ROWS_ / 128), 256, BIG_SMEM>>>(Wp, bp, y_out);
}